// round 3
// baseline (speedup 1.0000x reference)
#include <cuda_runtime.h>
#include <cuda_bf16.h>

// VariableSelectionNetwork: B=32, S=512, F=32, H=64
// Restructured as:
//   A[f][g] = sum_h W_feat[f,h] * W_gate[f*H+h, g]          (32x32)
//   c[g]    = b_gate[g] + sum_i b_feat[i] * W_gate[i, g]
//   gates   = softmax(x @ A + c)
//   X'      = [g*x (32), g (32)]   per row  (stored transposed, 64 x 16384)
//   out     = X' @ W'   with W' = [W_feat ; b_feat]  (64 x 64)

#define F_DIM 32
#define H_DIM 64
#define ROWS  16384   // B*S

// Device scratch (no allocations allowed)
__device__ float g_A[F_DIM * F_DIM];        // A[f][g]
__device__ float g_Cpart[F_DIM * F_DIM];    // per-f partial of c
__device__ float g_Xt[2 * F_DIM][ROWS];     // X' transposed: [k][row], 4 MB

// ---------------------------------------------------------------------------
// f32x2 packed helpers (Blackwell fp32 pipe, PTX 8.6 sm_100+)
// ---------------------------------------------------------------------------
__device__ __forceinline__ unsigned long long pk2(float a, float b) {
    unsigned long long r;
    asm("mov.b64 %0, {%1, %2};" : "=l"(r) : "f"(a), "f"(b));
    return r;
}
__device__ __forceinline__ void ffma2(unsigned long long& d,
                                      unsigned long long a,
                                      unsigned long long b) {
    asm("fma.rn.f32x2 %0, %1, %2, %3;" : "=l"(d) : "l"(a), "l"(b), "l"(d));
}
__device__ __forceinline__ float2 unpk2(unsigned long long v) {
    float2 r;
    asm("mov.b64 {%0, %1}, %2;" : "=f"(r.x), "=f"(r.y) : "l"(v));
    return r;
}

// ---------------------------------------------------------------------------
// Prep: 32 blocks (one per f), 256 threads. Builds A[f][:] and Cpart[f][:].
// ---------------------------------------------------------------------------
__global__ void __launch_bounds__(256) vsn_prep_kernel(
    const float* __restrict__ W_feat,   // [32,64]
    const float* __restrict__ b_feat,   // [32,64]
    const float* __restrict__ W_gate)   // [2048,32]
{
    const int f  = blockIdx.x;
    const int g  = threadIdx.x & 31;
    const int hs = threadIdx.x >> 5;    // 0..7

    float a = 0.f, c = 0.f;
#pragma unroll
    for (int k = 0; k < 8; k++) {
        const int h = hs * 8 + k;
        const float wg = W_gate[(f * H_DIM + h) * F_DIM + g];
        a = fmaf(W_feat[f * H_DIM + h], wg, a);
        c = fmaf(b_feat[f * H_DIM + h], wg, c);
    }

    __shared__ float sA[8][32];
    __shared__ float sC[8][32];
    sA[hs][g] = a;
    sC[hs][g] = c;
    __syncthreads();

    if (threadIdx.x < 32) {
        float as = 0.f, cs = 0.f;
#pragma unroll
        for (int r = 0; r < 8; r++) { as += sA[r][threadIdx.x]; cs += sC[r][threadIdx.x]; }
        g_A[f * F_DIM + threadIdx.x]     = as;
        g_Cpart[f * F_DIM + threadIdx.x] = cs;
    }
}

// ---------------------------------------------------------------------------
// Gates: 256 blocks x 256 threads, 4 threads/row (quad), 64 rows/block.
// Computes softmax gates and writes X' transposed to g_Xt.
// ---------------------------------------------------------------------------
__global__ void __launch_bounds__(256) vsn_gates_kernel(
    const float* __restrict__ features,  // [16384, 32]
    const float* __restrict__ b_gate)    // [32]
{
    __shared__ __align__(16) float sA[F_DIM * F_DIM];  // 4 KB
    __shared__ float sc[F_DIM];

    const int tid = threadIdx.x;

    // Stage A (exactly 256 float4) and fold c
    ((float4*)sA)[tid] = ((const float4*)g_A)[tid];
    if (tid < 32) {
        float cv = b_gate[tid];
#pragma unroll
        for (int f = 0; f < F_DIM; f++) cv += g_Cpart[f * F_DIM + tid];
        sc[tid] = cv;
    }
    __syncthreads();

    const int quad = tid >> 2;                 // row within block (0..63)
    const int q    = tid & 3;                  // role in quad
    const int row  = blockIdx.x * 64 + quad;

    // Full feature row in registers
    float x[F_DIM];
    {
        const float4* xr = (const float4*)(features + row * F_DIM);
#pragma unroll
        for (int i = 0; i < F_DIM / 4; i++) {
            float4 v = xr[i];
            x[4*i+0] = v.x; x[4*i+1] = v.y; x[4*i+2] = v.z; x[4*i+3] = v.w;
        }
    }

    // logits l[8] = x @ A[:, q*8 .. q*8+8) + c
    float l[8];
#pragma unroll
    for (int j = 0; j < 8; j++) l[j] = sc[q * 8 + j];
#pragma unroll
    for (int f = 0; f < F_DIM; f++) {
        const float xf = x[f];
        const float* arow = sA + f * F_DIM + q * 8;
#pragma unroll
        for (int j = 0; j < 8; j++) l[j] = fmaf(xf, arow[j], l[j]);
    }

    // Softmax across quad (32 logits)
    float m = l[0];
#pragma unroll
    for (int j = 1; j < 8; j++) m = fmaxf(m, l[j]);
    m = fmaxf(m, __shfl_xor_sync(0xffffffffu, m, 1));
    m = fmaxf(m, __shfl_xor_sync(0xffffffffu, m, 2));

    float s = 0.f;
#pragma unroll
    for (int j = 0; j < 8; j++) { l[j] = __expf(l[j] - m); s += l[j]; }
    s += __shfl_xor_sync(0xffffffffu, s, 1);
    s += __shfl_xor_sync(0xffffffffu, s, 2);

    const float inv = 1.f / s;
#pragma unroll
    for (int j = 0; j < 8; j++) l[j] *= inv;   // gates g[q*8+j]

    // Write X' transposed: k=f -> g*x[f];  k=32+f -> g
    const int fb = q * 8;
#pragma unroll
    for (int j = 0; j < 8; j++) {
        g_Xt[fb + j][row]          = l[j] * x[fb + j];
        g_Xt[F_DIM + fb + j][row]  = l[j];
    }
}

// ---------------------------------------------------------------------------
// GEMM: out[16384,64] = X'[16384,64] @ W'[64,64],  W' = [W_feat ; b_feat].
// 512 blocks x 128 threads. Block tile = 64 rows x 32 cols.
// Thread tile = 4 rows x 4 cols, accumulated as f32x2 pairs.
// ---------------------------------------------------------------------------
__global__ void __launch_bounds__(128) vsn_gemm_kernel(
    const float* __restrict__ W_feat,   // [32,64]
    const float* __restrict__ b_feat,   // [32,64]
    float* __restrict__ out)            // [16384,64]
{
    __shared__ __align__(16) float sW[2 * F_DIM][32];   // 8 KB: [k][col-in-half]

    const int tid   = threadIdx.x;
    const int chalf = blockIdx.x & 1;          // which 32-col half of H
    const int row0  = (blockIdx.x >> 1) * 64;
    const int c0    = chalf * 32;

    // Stage this block's 32-column slice of W' (64 rows x 32 floats)
#pragma unroll
    for (int i = tid; i < 512; i += 128) {     // 512 float4
        const int k   = i >> 3;                // 8 float4 per k-row
        const int seg = i & 7;
        const float* src = (k < F_DIM ? W_feat + k * H_DIM
                                      : b_feat + (k - F_DIM) * H_DIM) + c0 + seg * 4;
        *(float4*)&sW[k][seg * 4] = *(const float4*)src;
    }
    __syncthreads();

    const int c  = tid & 7;        // colgroup: 4 contiguous cols at c0 + c*4
    const int rg = tid >> 3;       // rowgroup: 4 contiguous rows at row0 + rg*4
    const int r0 = row0 + rg * 4;

    unsigned long long acc[4][2];
#pragma unroll
    for (int r = 0; r < 4; r++) { acc[r][0] = 0ull; acc[r][1] = 0ull; }

    const float* __restrict__ xt = &g_Xt[0][0];

#pragma unroll 8
    for (int k = 0; k < 2 * F_DIM; k++) {
        const float4 xv = __ldg((const float4*)(xt + k * ROWS + r0));
        const ulonglong2 wv = *(const ulonglong2*)&sW[k][c * 4];

        const unsigned long long xp0 = pk2(xv.x, xv.x);
        const unsigned long long xp1 = pk2(xv.y, xv.y);
        const unsigned long long xp2 = pk2(xv.z, xv.z);
        const unsigned long long xp3 = pk2(xv.w, xv.w);

        ffma2(acc[0][0], xp0, wv.x); ffma2(acc[0][1], xp0, wv.y);
        ffma2(acc[1][0], xp1, wv.x); ffma2(acc[1][1], xp1, wv.y);
        ffma2(acc[2][0], xp2, wv.x); ffma2(acc[2][1], xp2, wv.y);
        ffma2(acc[3][0], xp3, wv.x); ffma2(acc[3][1], xp3, wv.y);
    }

    // Store 4 rows x 4 cols
#pragma unroll
    for (int r = 0; r < 4; r++) {
        const float2 lo = unpk2(acc[r][0]);
        const float2 hi = unpk2(acc[r][1]);
        *(float4*)(out + (r0 + r) * H_DIM + c0 + c * 4) =
            make_float4(lo.x, lo.y, hi.x, hi.y);
    }
}

extern "C" void kernel_launch(void* const* d_in, const int* in_sizes, int n_in,
                              void* d_out, int out_size)
{
    const float* features = (const float*)d_in[0];   // [32,512,32]
    const float* W_feat   = (const float*)d_in[1];   // [32,64]
    const float* b_feat   = (const float*)d_in[2];   // [32,64]
    const float* W_gate   = (const float*)d_in[3];   // [2048,32]
    const float* b_gate   = (const float*)d_in[4];   // [32]
    float* out = (float*)d_out;                      // [32,512,64]

    vsn_prep_kernel<<<32, 256>>>(W_feat, b_feat, W_gate);
    vsn_gates_kernel<<<256, 256>>>(features, b_gate);
    vsn_gemm_kernel<<<512, 128>>>(W_feat, b_feat, out);
}

// round 4
// speedup vs baseline: 2.3022x; 2.3022x over previous
#include <cuda_runtime.h>
#include <cuda_bf16.h>

// VariableSelectionNetwork: B=32, S=512, F=32, H=64
//   A[f][g] = sum_h W_feat[f,h]*W_gate[f*H+h, g];  c[g] = b_gate[g] + sum b_feat.W_gate
//   gates = softmax(x @ A + c);  out = [g*x, g] @ [W_feat; b_feat]
// Kernel 1 (prep): partial A/c over 4 h-quarters, 128 blocks.
// Kernel 2 (main): fused gates + 64x64 GEMM, X' staged in smem, f32x2 FMAs.

#define F_DIM 32
#define H_DIM 64
#define ROWS  16384
#define MB_ROWS 128          // rows per main block
#define MAIN_GRID (ROWS / MB_ROWS)   // 128

// Device scratch
__device__ float g_Apart[4 * 1024];   // [q][f*32+g]
__device__ float g_Cpart[4 * 1024];   // [q][f*32+g]

// ---------------- f32x2 helpers (validated on sm_100a in prior round) ------
__device__ __forceinline__ unsigned long long pk2(float a, float b) {
    unsigned long long r;
    asm("mov.b64 %0, {%1, %2};" : "=l"(r) : "f"(a), "f"(b));
    return r;
}
__device__ __forceinline__ void ffma2(unsigned long long& d,
                                      unsigned long long a,
                                      unsigned long long b) {
    asm("fma.rn.f32x2 %0, %1, %2, %3;" : "=l"(d) : "l"(a), "l"(b), "l"(d));
}
__device__ __forceinline__ float2 unpk2(unsigned long long v) {
    float2 r;
    asm("mov.b64 {%0, %1}, %2;" : "=f"(r.x), "=f"(r.y) : "l"(v));
    return r;
}

// ---------------------------------------------------------------------------
// Prep: 128 blocks (f = bid>>2, h-quarter q = bid&3), 128 threads.
// ---------------------------------------------------------------------------
__global__ void __launch_bounds__(128) vsn_prep_kernel(
    const float* __restrict__ W_feat,   // [32,64]
    const float* __restrict__ b_feat,   // [32,64]
    const float* __restrict__ W_gate)   // [2048,32]
{
    const int f  = blockIdx.x >> 2;
    const int q  = blockIdx.x & 3;
    const int g  = threadIdx.x & 31;
    const int hh = threadIdx.x >> 5;    // 0..3

    float a = 0.f, c = 0.f;
#pragma unroll
    for (int kk = 0; kk < 4; kk++) {
        const int h = q * 16 + hh * 4 + kk;
        const float wg = W_gate[(f * H_DIM + h) * F_DIM + g];
        a = fmaf(W_feat[f * H_DIM + h], wg, a);
        c = fmaf(b_feat[f * H_DIM + h], wg, c);
    }

    __shared__ float rA[4][32];
    __shared__ float rC[4][32];
    rA[hh][g] = a;
    rC[hh][g] = c;
    __syncthreads();

    if (threadIdx.x < 32) {
        float as = 0.f, cs = 0.f;
#pragma unroll
        for (int r = 0; r < 4; r++) { as += rA[r][threadIdx.x]; cs += rC[r][threadIdx.x]; }
        g_Apart[q * 1024 + f * F_DIM + threadIdx.x] = as;
        g_Cpart[q * 1024 + f * F_DIM + threadIdx.x] = cs;
    }
}

// ---------------------------------------------------------------------------
// Main: 128 blocks x 256 threads, 128 rows per block. Dynamic smem:
//   sWB [64][64]  (16 KB)  combined [W_feat; b_feat]
//   sX  [64][128] (32 KB)  X' k-major; reused as partial buffer for split-k
//   sA  [32][32]  ( 4 KB)
// ---------------------------------------------------------------------------
__global__ void __launch_bounds__(256, 1) vsn_main_kernel(
    const float* __restrict__ features,  // [16384,32]
    const float* __restrict__ W_feat,    // [32,64]
    const float* __restrict__ b_feat,    // [32,64]
    const float* __restrict__ b_gate,    // [32]
    float* __restrict__ out)             // [16384,64]
{
    extern __shared__ float smem[];
    float* sWB = smem;                 // 4096 floats
    float* sX  = smem + 4096;          // 8192 floats
    float* sA  = smem + 4096 + 8192;   // 1024 floats

    __shared__ __align__(16) float sc[32];
    __shared__ float sCred[8][32];

    const int tid = threadIdx.x;

    // ---- Stage ----
#pragma unroll
    for (int i = tid; i < 1024; i += 256) {        // sWB: 1024 float4
        const int k   = i >> 4;
        const int seg = i & 15;
        const float* src = (k < F_DIM ? W_feat + k * H_DIM
                                      : b_feat + (k - F_DIM) * H_DIM) + seg * 4;
        *(float4*)(sWB + k * H_DIM + seg * 4) = *(const float4*)src;
    }
#pragma unroll
    for (int j = 0; j < 4; j++) {                  // sA = sum of 4 partials
        const int i = tid + j * 256;
        sA[i] = g_Apart[i] + g_Apart[1024 + i] + g_Apart[2048 + i] + g_Apart[3072 + i];
    }
    {                                              // sc partials
        const int g  = tid & 31;
        const int ch = tid >> 5;                   // 0..7
        float s = 0.f;
#pragma unroll
        for (int e = 0; e < 16; e++) {
            const int ee = ch * 16 + e;            // (q,f) flat index 0..127
            s += g_Cpart[(ee >> 5) * 1024 + (ee & 31) * F_DIM + g];
        }
        sCred[ch][g] = s;
    }
    __syncthreads();
    if (tid < 32) {
        float cv = b_gate[tid];
#pragma unroll
        for (int r = 0; r < 8; r++) cv += sCred[r][tid];
        sc[tid] = cv;
    }
    __syncthreads();

    // ---- Phase 1: gates (2 threads per row, 16 logits each) ----
    const int rowL  = tid >> 1;                    // 0..127
    const int half  = tid & 1;
    const int fbase = half * 16;
    const int row   = blockIdx.x * MB_ROWS + rowL;

    float x[F_DIM];
    {
        const float4* xr = (const float4*)(features + row * F_DIM);
#pragma unroll
        for (int i = 0; i < 8; i++) {
            float4 v = xr[i];
            x[4*i+0] = v.x; x[4*i+1] = v.y; x[4*i+2] = v.z; x[4*i+3] = v.w;
        }
    }

    unsigned long long l2[8];
    {
        const ulonglong2* cp = (const ulonglong2*)(sc + fbase);
        ulonglong2 c0 = cp[0], c1 = cp[1], c2 = cp[2], c3 = cp[3];
        l2[0]=c0.x; l2[1]=c0.y; l2[2]=c1.x; l2[3]=c1.y;
        l2[4]=c2.x; l2[5]=c2.y; l2[6]=c3.x; l2[7]=c3.y;
    }
#pragma unroll
    for (int f = 0; f < F_DIM; f++) {
        const unsigned long long xp = pk2(x[f], x[f]);
        const ulonglong2* ap = (const ulonglong2*)(sA + f * F_DIM + fbase);
        ulonglong2 a0 = ap[0], a1 = ap[1], a2 = ap[2], a3 = ap[3];
        ffma2(l2[0], xp, a0.x); ffma2(l2[1], xp, a0.y);
        ffma2(l2[2], xp, a1.x); ffma2(l2[3], xp, a1.y);
        ffma2(l2[4], xp, a2.x); ffma2(l2[5], xp, a2.y);
        ffma2(l2[6], xp, a3.x); ffma2(l2[7], xp, a3.y);
    }
    float le[16];
#pragma unroll
    for (int i = 0; i < 8; i++) {
        float2 v = unpk2(l2[i]);
        le[2*i] = v.x; le[2*i+1] = v.y;
    }

    // Softmax: 16 local + partner (lane^1)
    float m = le[0];
#pragma unroll
    for (int j = 1; j < 16; j++) m = fmaxf(m, le[j]);
    m = fmaxf(m, __shfl_xor_sync(0xffffffffu, m, 1));
    float s = 0.f;
#pragma unroll
    for (int j = 0; j < 16; j++) { le[j] = __expf(le[j] - m); s += le[j]; }
    s += __shfl_xor_sync(0xffffffffu, s, 1);
    const float inv = 1.f / s;

    // Write X' (k-major): sX[f][rowL] = g*x[f]; sX[32+f][rowL] = g
    if (half == 0) {
#pragma unroll
        for (int j = 0; j < 16; j++) {
            const float gj = le[j] * inv;
            sX[j * MB_ROWS + rowL]              = gj * x[j];
            sX[(F_DIM + j) * MB_ROWS + rowL]    = gj;
        }
    } else {
#pragma unroll
        for (int j = 0; j < 16; j++) {
            const float gj = le[j] * inv;
            sX[(16 + j) * MB_ROWS + rowL]           = gj * x[16 + j];
            sX[(F_DIM + 16 + j) * MB_ROWS + rowL]   = gj;
        }
    }
    __syncthreads();

    // ---- Phase 2: out = X' @ W', split-k over 2 halves, 8x8 thread tiles ----
    const int kh = tid >> 7;        // 0 or 1
    const int tt = tid & 127;
    const int rg = tt >> 3;         // 0..15 -> rows rg*8..+8
    const int cg = tt & 7;          // cols cg*8..+8
    const int r0 = rg * 8;
    const int c0 = cg * 8;

    unsigned long long acc[8][4];
#pragma unroll
    for (int r = 0; r < 8; r++)
#pragma unroll
        for (int p = 0; p < 4; p++) acc[r][p] = 0ull;

#pragma unroll 8
    for (int kk = 0; kk < 32; kk++) {
        const int k = kh * 32 + kk;
        const float4* xp4 = (const float4*)(sX + k * MB_ROWS + r0);
        const float4 xa = xp4[0], xb = xp4[1];
        unsigned long long xq[8];
        xq[0] = pk2(xa.x, xa.x); xq[1] = pk2(xa.y, xa.y);
        xq[2] = pk2(xa.z, xa.z); xq[3] = pk2(xa.w, xa.w);
        xq[4] = pk2(xb.x, xb.x); xq[5] = pk2(xb.y, xb.y);
        xq[6] = pk2(xb.z, xb.z); xq[7] = pk2(xb.w, xb.w);

        const ulonglong2* wp = (const ulonglong2*)(sWB + k * H_DIM + c0);
        const ulonglong2 w0 = wp[0], w1 = wp[1];   // 4 col-pairs

#pragma unroll
        for (int r = 0; r < 8; r++) {
            ffma2(acc[r][0], xq[r], w0.x);
            ffma2(acc[r][1], xq[r], w0.y);
            ffma2(acc[r][2], xq[r], w1.x);
            ffma2(acc[r][3], xq[r], w1.y);
        }
    }
    __syncthreads();   // all reads of sX done; reuse as partial buffer

    // kh=1 writes partials (element-major: conflict-free, 64*128 = 8192 floats)
    if (kh == 1) {
#pragma unroll
        for (int r = 0; r < 8; r++)
#pragma unroll
            for (int p = 0; p < 4; p++) {
                const float2 v = unpk2(acc[r][p]);
                sX[(r * 8 + p * 2 + 0) * 128 + tt] = v.x;
                sX[(r * 8 + p * 2 + 1) * 128 + tt] = v.y;
            }
    }
    __syncthreads();

    if (kh == 0) {
        const int rowbase = blockIdx.x * MB_ROWS + r0;
#pragma unroll
        for (int r = 0; r < 8; r++) {
            const float2 v0 = unpk2(acc[r][0]);
            const float2 v1 = unpk2(acc[r][1]);
            const float2 v2 = unpk2(acc[r][2]);
            const float2 v3 = unpk2(acc[r][3]);
            float4 o0 = make_float4(
                v0.x + sX[(r*8+0)*128 + tt], v0.y + sX[(r*8+1)*128 + tt],
                v1.x + sX[(r*8+2)*128 + tt], v1.y + sX[(r*8+3)*128 + tt]);
            float4 o1 = make_float4(
                v2.x + sX[(r*8+4)*128 + tt], v2.y + sX[(r*8+5)*128 + tt],
                v3.x + sX[(r*8+6)*128 + tt], v3.y + sX[(r*8+7)*128 + tt]);
            float* dst = out + (rowbase + r) * H_DIM + c0;
            *(float4*)(dst)     = o0;
            *(float4*)(dst + 4) = o1;
        }
    }
}

extern "C" void kernel_launch(void* const* d_in, const int* in_sizes, int n_in,
                              void* d_out, int out_size)
{
    const float* features = (const float*)d_in[0];   // [32,512,32]
    const float* W_feat   = (const float*)d_in[1];   // [32,64]
    const float* b_feat   = (const float*)d_in[2];   // [32,64]
    const float* W_gate   = (const float*)d_in[3];   // [2048,32]
    const float* b_gate   = (const float*)d_in[4];   // [32]
    float* out = (float*)d_out;                      // [32,512,64]

    const int smem_bytes = (4096 + 8192 + 1024) * 4;  // 53248
    cudaFuncSetAttribute(vsn_main_kernel,
                         cudaFuncAttributeMaxDynamicSharedMemorySize, smem_bytes);

    vsn_prep_kernel<<<128, 128>>>(W_feat, b_feat, W_gate);
    vsn_main_kernel<<<MAIN_GRID, 256, smem_bytes>>>(features, W_feat, b_feat, b_gate, out);
}